// round 1
// baseline (speedup 1.0000x reference)
#include <cuda_runtime.h>

// ---------------------------------------------------------------------------
// Fused LSTMMeasurementPredictor
//   B=131072, H=128, NQ=2, P=32, D_IN=17, T=16
// One persistent time loop per 64-batch tile; all state in shared memory.
// ---------------------------------------------------------------------------

#define NTH 256
#define BT  64
#define SS_ 68   // padded row stride (floats) for [K][64] smem buffers

// smem layout offsets (floats)
constexpr int OFF_X   = 0;                  // 17  rows : x (17-dim input)
constexpr int OFF_HC  = OFF_X  + 17 * SS_;  // 128 rows : cell h
constexpr int OFF_CC  = OFF_HC + 128 * SS_; // 128 rows : cell c
constexpr int OFF_H0  = OFF_CC + 128 * SS_; // 32  rows : lstm0 proj h
constexpr int OFF_C0  = OFF_H0 + 32 * SS_;  // 128 rows : lstm0 c
constexpr int OFF_H1  = OFF_C0 + 128 * SS_; // 32  rows : lstm1 proj h
constexpr int OFF_C1  = OFF_H1 + 32 * SS_;  // 128 rows : lstm1 c
constexpr int OFF_S   = OFF_C1 + 128 * SS_; // 128 rows : s / h_new staging
constexpr int OFF_RHO = OFF_S  + 128 * SS_; // 64*33    : rho (b-major, pad 33)
constexpr int OFF_V   = OFF_RHO + 64 * 33;  // 8 rows   : projector v
constexpr int SMEM_FLOATS = OFF_V + 8 * SS_;
constexpr int SMEM_BYTES  = SMEM_FLOATS * 4;  // ~207 KB

// packed weights (prep kernel fills these)
// layout: W[k][512] with column jp = u*4 + gate  (gate order i,f,g,o)
__device__ __align__(16) float g_Wc[145 * 512];   // cell: [x(17); h(128)]
__device__ __align__(16) float g_bc[512];
__device__ __align__(16) float g_W0[49 * 512];    // lstm0: [x(17); hp(32)]
__device__ __align__(16) float g_b0[512];
__device__ __align__(16) float g_W1[64 * 512];    // lstm1: [hp0(32); hp1(32)]
__device__ __align__(16) float g_b1[512];
__device__ __align__(16) float g_Whr0T[128 * 32];
__device__ __align__(16) float g_Whr1T[128 * 32];
__device__ __align__(16) float g_WpT[128 * 8];

__global__ void prep_kernel(
    const float* __restrict__ Wihc, const float* __restrict__ Whhc,
    const float* __restrict__ bihc, const float* __restrict__ bhhc,
    const float* __restrict__ Wp,
    const float* __restrict__ Wih0, const float* __restrict__ Whh0,
    const float* __restrict__ bih0, const float* __restrict__ bhh0,
    const float* __restrict__ Whr0,
    const float* __restrict__ Wih1, const float* __restrict__ Whh1,
    const float* __restrict__ bih1, const float* __restrict__ bhh1,
    const float* __restrict__ Whr1)
{
    int i0 = blockIdx.x * blockDim.x + threadIdx.x;
    int stride = gridDim.x * blockDim.x;

    for (int i = i0; i < 145 * 512; i += stride) {
        int k = i >> 9, jp = i & 511;
        int u = jp >> 2, g = jp & 3, j = g * 128 + u;
        g_Wc[i] = (k < 17) ? Wihc[j * 17 + k] : Whhc[j * 128 + (k - 17)];
    }
    for (int i = i0; i < 49 * 512; i += stride) {
        int k = i >> 9, jp = i & 511;
        int u = jp >> 2, g = jp & 3, j = g * 128 + u;
        g_W0[i] = (k < 17) ? Wih0[j * 17 + k] : Whh0[j * 32 + (k - 17)];
    }
    for (int i = i0; i < 64 * 512; i += stride) {
        int k = i >> 9, jp = i & 511;
        int u = jp >> 2, g = jp & 3, j = g * 128 + u;
        g_W1[i] = (k < 32) ? Wih1[j * 32 + k] : Whh1[j * 32 + (k - 32)];
    }
    for (int i = i0; i < 512; i += stride) {
        int u = i >> 2, g = i & 3, j = g * 128 + u;
        g_bc[i] = bihc[j] + bhhc[j];
        g_b0[i] = bih0[j] + bhh0[j];
        g_b1[i] = bih1[j] + bhh1[j];
    }
    for (int i = i0; i < 128 * 32; i += stride) {
        int k = i >> 5, n = i & 31;
        g_Whr0T[i] = Whr0[n * 128 + k];
        g_Whr1T[i] = Whr1[n * 128 + k];
    }
    for (int i = i0; i < 128 * 8; i += stride) {
        int k = i >> 3, n = i & 7;
        g_WpT[i] = Wp[n * 128 + k];
    }
}

// ---------------------------------------------------------------------------
__device__ __forceinline__ float fsig(float x) {
    return __fdividef(1.0f, 1.0f + __expf(-x));
}
__device__ __forceinline__ float ftanh(float x) {
    // 2/(1+exp(-2x)) - 1 ; robust at +/- inf
    return __fdividef(2.0f, 1.0f + __expf(-2.0f * x)) - 1.0f;
}

// One LSTM gate GEMM + elementwise update.
// Computes G[64,512] = [A(KA); B(KB)] @ W + bias, gate-interleaved columns.
// Thread (n_t=tid&31, b_t=tid>>5) handles unit u=cc*32+n_t, batches b_t*8..+7.
template <int KA, int KB>
__device__ __forceinline__ void lstm_gemm(
    const float* __restrict__ W, const float* __restrict__ bias,
    const float* shA, const float* shB, float* shC, float* shOut,
    int n_t, int b_t)
{
    const int b0 = b_t * 8;
#pragma unroll 1
    for (int cc = 0; cc < 4; ++cc) {
        const int ncol = cc * 128 + n_t * 4;
        float4 bs = *(const float4*)(bias + ncol);
        float acc[4][8];
#pragma unroll
        for (int bb = 0; bb < 8; ++bb) {
            acc[0][bb] = bs.x; acc[1][bb] = bs.y;
            acc[2][bb] = bs.z; acc[3][bb] = bs.w;
        }
        const float* Wa = W + ncol;
#pragma unroll 4
        for (int k = 0; k < KA; ++k) {
            float4 w = __ldg((const float4*)(Wa + k * 512));
            float4 a0 = *(const float4*)(shA + k * SS_ + b0);
            float4 a1 = *(const float4*)(shA + k * SS_ + b0 + 4);
            float av[8] = {a0.x, a0.y, a0.z, a0.w, a1.x, a1.y, a1.z, a1.w};
#pragma unroll
            for (int bb = 0; bb < 8; ++bb) {
                acc[0][bb] += w.x * av[bb];
                acc[1][bb] += w.y * av[bb];
                acc[2][bb] += w.z * av[bb];
                acc[3][bb] += w.w * av[bb];
            }
        }
        const float* Wb = W + KA * 512 + ncol;
#pragma unroll 4
        for (int k = 0; k < KB; ++k) {
            float4 w = __ldg((const float4*)(Wb + k * 512));
            float4 a0 = *(const float4*)(shB + k * SS_ + b0);
            float4 a1 = *(const float4*)(shB + k * SS_ + b0 + 4);
            float av[8] = {a0.x, a0.y, a0.z, a0.w, a1.x, a1.y, a1.z, a1.w};
#pragma unroll
            for (int bb = 0; bb < 8; ++bb) {
                acc[0][bb] += w.x * av[bb];
                acc[1][bb] += w.y * av[bb];
                acc[2][bb] += w.z * av[bb];
                acc[3][bb] += w.w * av[bb];
            }
        }
        // epilogue: gate nonlinearities, c update, s = sig(o)*tanh(c_new)
        const int u = cc * 32 + n_t;
        float4 c0v = *(const float4*)(shC + u * SS_ + b0);
        float4 c1v = *(const float4*)(shC + u * SS_ + b0 + 4);
        float cv[8] = {c0v.x, c0v.y, c0v.z, c0v.w, c1v.x, c1v.y, c1v.z, c1v.w};
#pragma unroll
        for (int bb = 0; bb < 8; ++bb) {
            float gi = fsig(acc[0][bb]);
            float gf = fsig(acc[1][bb]);
            float gg = ftanh(acc[2][bb]);
            float go = fsig(acc[3][bb]);
            float cn = gf * cv[bb] + gi * gg;
            cv[bb] = cn;
            shOut[u * SS_ + b0 + bb] = go * ftanh(cn);
        }
        *(float4*)(shC + u * SS_ + b0)     = make_float4(cv[0], cv[1], cv[2], cv[3]);
        *(float4*)(shC + u * SS_ + b0 + 4) = make_float4(cv[4], cv[5], cv[6], cv[7]);
    }
}

// hp[64,32] = s[64,128] @ WhrT[128,32]; optionally also store to global out.
__device__ __forceinline__ void proj_gemm(
    const float* __restrict__ WT, const float* shS, float* shHdst,
    float* outp, int tid)
{
    const int n4 = (tid & 7) * 4;
    const int b  = (tid >> 3) * 2;
    float acc[4][2] = {{0.f, 0.f}, {0.f, 0.f}, {0.f, 0.f}, {0.f, 0.f}};
#pragma unroll 4
    for (int k = 0; k < 128; ++k) {
        float4 w = __ldg((const float4*)(WT + k * 32 + n4));
        float s0 = shS[k * SS_ + b];
        float s1 = shS[k * SS_ + b + 1];
        acc[0][0] += w.x * s0; acc[0][1] += w.x * s1;
        acc[1][0] += w.y * s0; acc[1][1] += w.y * s1;
        acc[2][0] += w.z * s0; acc[2][1] += w.z * s1;
        acc[3][0] += w.w * s0; acc[3][1] += w.w * s1;
    }
#pragma unroll
    for (int g = 0; g < 4; ++g) {
        shHdst[(n4 + g) * SS_ + b]     = acc[g][0];
        shHdst[(n4 + g) * SS_ + b + 1] = acc[g][1];
    }
    if (outp) {
        *(float4*)(outp + (size_t)b * 512 + n4) =
            make_float4(acc[0][0], acc[1][0], acc[2][0], acc[3][0]);
        *(float4*)(outp + (size_t)(b + 1) * 512 + n4) =
            make_float4(acc[0][1], acc[1][1], acc[2][1], acc[3][1]);
    }
}

// quantum measurement physics for one batch element b (0..63)
__device__ __forceinline__ void physics(const float* shV, const float* shRHO,
                                        float* shX, int b)
{
    float Mr[2][2][2], Mi[2][2][2];
#pragma unroll
    for (int q = 0; q < 2; ++q) {
        float ar = shV[(q * 4 + 0) * SS_ + b];
        float ai = shV[(q * 4 + 1) * SS_ + b];
        float br = shV[(q * 4 + 2) * SS_ + b];
        float bi = shV[(q * 4 + 3) * SS_ + b];
        float n00 = ar * ar + ai * ai;
        float n11 = br * br + bi * bi;
        float inv = 1.0f / (n00 + n11);
        float pr = (ar * br + ai * bi) * inv;
        float pi = (ai * br - ar * bi) * inv;
        Mr[q][0][0] = n00 * inv; Mi[q][0][0] = 0.f;
        Mr[q][0][1] = pr;        Mi[q][0][1] = pi;
        Mr[q][1][0] = pr;        Mi[q][1][0] = -pi;
        Mr[q][1][1] = n11 * inv; Mi[q][1][1] = 0.f;
    }
    const float* rp = shRHO + b * 33;
    float m = 0.f;
#pragma unroll
    for (int a = 0; a < 2; ++a)
#pragma unroll
        for (int c = 0; c < 2; ++c)
#pragma unroll
            for (int b2 = 0; b2 < 2; ++b2)
#pragma unroll
                for (int d = 0; d < 2; ++d) {
                    float tr_ = Mr[0][a][c] * Mr[1][b2][d] - Mi[0][a][c] * Mi[1][b2][d];
                    float ti_ = Mr[0][a][c] * Mi[1][b2][d] + Mi[0][a][c] * Mr[1][b2][d];
                    int row = c * 2 + d, col = a * 2 + b2;
                    float rr = rp[row * 4 + col];
                    float ri = rp[16 + row * 4 + col];
                    m += tr_ * rr - ti_ * ri;
                }
    shX[0 * SS_ + b] = m;
#pragma unroll
    for (int q = 0; q < 2; ++q)
#pragma unroll
        for (int i = 0; i < 2; ++i)
#pragma unroll
            for (int j = 0; j < 2; ++j) {
                int base = 1 + 8 * q + 4 * i + 2 * j;
                shX[base * SS_ + b]       = Mr[q][i][j];
                shX[(base + 1) * SS_ + b] = Mi[q][i][j];
            }
}

__global__ void __launch_bounds__(NTH, 1) fused_kernel(
    const float* __restrict__ meas, const float* __restrict__ basis_r,
    const float* __restrict__ basis_i, const float* __restrict__ rho,
    const float* __restrict__ h0in, const float* __restrict__ c0in,
    const float* __restrict__ bp, float* __restrict__ out)
{
    extern __shared__ float sm[];
    float* shX   = sm + OFF_X;
    float* shHC  = sm + OFF_HC;
    float* shCC  = sm + OFF_CC;
    float* shH0  = sm + OFF_H0;
    float* shC0  = sm + OFF_C0;
    float* shH1  = sm + OFF_H1;
    float* shC1  = sm + OFF_C1;
    float* shS   = sm + OFF_S;
    float* shRHO = sm + OFF_RHO;
    float* shV   = sm + OFF_V;

    const int tid = threadIdx.x;
    const int b0g = blockIdx.x * BT;

    // ---- init loads ----
    for (int i = tid; i < BT; i += NTH)
        shX[0 * SS_ + i] = meas[b0g + i];
    for (int i = tid; i < BT * 8; i += NTH) {
        int b = i >> 3, e = i & 7;
        shX[(1 + 2 * e) * SS_ + b] = basis_r[(size_t)(b0g + b) * 8 + e];
        shX[(2 + 2 * e) * SS_ + b] = basis_i[(size_t)(b0g + b) * 8 + e];
    }
    for (int i = tid; i < BT * 32; i += NTH) {
        int b = i >> 5, e = i & 31;
        shRHO[b * 33 + e] = rho[(size_t)(b0g + b) * 32 + e];
    }
    for (int i = tid; i < BT * 128; i += NTH) {
        int b = i >> 7, u = i & 127;
        shHC[u * SS_ + b] = h0in[(size_t)(b0g + b) * 128 + u];
        shCC[u * SS_ + b] = c0in[(size_t)(b0g + b) * 128 + u];
    }
    // zero h0/c0/h1/c1 (320 consecutive rows starting at OFF_H0)
    for (int i = tid; i < 320 * SS_; i += NTH)
        sm[OFF_H0 + i] = 0.f;
    __syncthreads();

    const int n_t = tid & 31;
    const int b_t = tid >> 5;

    for (int t = 0; t < 16; ++t) {
        // LSTM0 step: input [x(17); hp0(32)]
        lstm_gemm<17, 32>(g_W0, g_b0, shX, shH0, shC0, shS, n_t, b_t);
        __syncthreads();
        proj_gemm(g_Whr0T, shS, shH0, nullptr, tid);
        __syncthreads();
        // LSTM1 step: input [hp0(32); hp1(32)]
        lstm_gemm<32, 32>(g_W1, g_b1, shH0, shH1, shC1, shS, n_t, b_t);
        __syncthreads();
        proj_gemm(g_Whr1T, shS, shH1,
                  out + (size_t)b0g * 512 + (size_t)t * 32, tid);
        __syncthreads();

        if (t < 15) {
            // cell step: input [x(17); h_cell(128)]; h_new staged into shS
            lstm_gemm<17, 128>(g_Wc, g_bc, shX, shHC, shCC, shS, n_t, b_t);
            __syncthreads();
            // projector v[64,8] = h_new @ WpT + bp
            for (int idx = tid; idx < 512; idx += NTH) {
                int nn = idx >> 6, bb = idx & 63;
                float a = __ldg(&bp[nn]);
#pragma unroll 4
                for (int k = 0; k < 128; ++k)
                    a += shS[k * SS_ + bb] * __ldg(&g_WpT[k * 8 + nn]);
                shV[nn * SS_ + bb] = a;
            }
            __syncthreads();
            // physics -> new x ; copy h_new (shS) -> shHC
            if (tid < BT) physics(shV, shRHO, shX, tid);
            for (int i = tid; i < 128 * BT; i += NTH) {
                int u = i >> 6, b = i & 63;
                shHC[u * SS_ + b] = shS[u * SS_ + b];
            }
            __syncthreads();
        }
    }
}

extern "C" void kernel_launch(void* const* d_in, const int* in_sizes, int n_in,
                              void* d_out, int out_size)
{
    const float* meas   = (const float*)d_in[0];
    const float* br     = (const float*)d_in[1];
    const float* bi     = (const float*)d_in[2];
    const float* rho    = (const float*)d_in[3];
    const float* h0     = (const float*)d_in[4];
    const float* c0     = (const float*)d_in[5];
    const float* Wihc   = (const float*)d_in[6];
    const float* Whhc   = (const float*)d_in[7];
    const float* bihc   = (const float*)d_in[8];
    const float* bhhc   = (const float*)d_in[9];
    const float* Wp     = (const float*)d_in[10];
    const float* bp     = (const float*)d_in[11];
    const float* Wih0   = (const float*)d_in[12];
    const float* Whh0   = (const float*)d_in[13];
    const float* bih0   = (const float*)d_in[14];
    const float* bhh0   = (const float*)d_in[15];
    const float* Whr0   = (const float*)d_in[16];
    const float* Wih1   = (const float*)d_in[17];
    const float* Whh1   = (const float*)d_in[18];
    const float* bih1   = (const float*)d_in[19];
    const float* bhh1   = (const float*)d_in[20];
    const float* Whr1   = (const float*)d_in[21];

    int B = in_sizes[0];            // measurement is (B,1)
    int nblocks = B / BT;

    cudaFuncSetAttribute(fused_kernel,
                         cudaFuncAttributeMaxDynamicSharedMemorySize,
                         SMEM_BYTES);

    prep_kernel<<<128, 256>>>(Wihc, Whhc, bihc, bhhc, Wp,
                              Wih0, Whh0, bih0, bhh0, Whr0,
                              Wih1, Whh1, bih1, bhh1, Whr1);

    fused_kernel<<<nblocks, NTH, SMEM_BYTES>>>(
        meas, br, bi, rho, h0, c0, bp, (float*)d_out);
}